// round 14
// baseline (speedup 1.0000x reference)
#include <cuda_runtime.h>
#include <cuda_fp16.h>
#include <math.h>
#include <stdint.h>

#define T_TOK 4096
#define H_DIM 768
#define I_DIM 1152
#define TWO_I 2304
#define E_NUM 8

// ---------------- device-global scratch ------------------------------------
__device__ int    g_count[E_NUM];               // zero-init; re-zeroed by final_add
__device__ int    g_tok[E_NUM * T_TOK];
__device__ int    g_dst[E_NUM * T_TOK];
__device__ float  g_w  [E_NUM * T_TOK];
__device__ __half g_act[(size_t)E_NUM * T_TOK * I_DIM];  // expert GLU out
__device__ __half g_as [(size_t)T_TOK * I_DIM];          // shared GLU out
__device__ float  g_par[(size_t)T_TOK * 2 * H_DIM];      // per-(t,k) down-proj
__device__ __half g_hx   [(size_t)T_TOK * H_DIM];        // x fp16
__device__ __half g_hwi  [(size_t)E_NUM * H_DIM * TWO_I];// Wi fp16 [K][2I]
__device__ __half g_hwo  [(size_t)E_NUM * I_DIM * H_DIM];// Wo fp16 [K][N]
__device__ __half g_hswiT[(size_t)H_DIM * TWO_I];        // sWi^T fp16 [K][2I]
__device__ __half g_hswoT[(size_t)I_DIM * H_DIM];        // sWo^T fp16 [K][N]

// ---------------- PTX helpers ------------------------------------------------
__device__ __forceinline__ float silu_f(float v) { return v / (1.f + __expf(-v)); }

__device__ __forceinline__ void mma16(float* c, const uint32_t* a, const uint32_t* b) {
    asm volatile(
        "mma.sync.aligned.m16n8k16.row.col.f32.f16.f16.f32 "
        "{%0,%1,%2,%3},{%4,%5,%6,%7},{%8,%9},{%0,%1,%2,%3};"
        : "+f"(c[0]), "+f"(c[1]), "+f"(c[2]), "+f"(c[3])
        : "r"(a[0]), "r"(a[1]), "r"(a[2]), "r"(a[3]), "r"(b[0]), "r"(b[1]));
}
__device__ __forceinline__ void ldsm4(uint32_t* r, uint32_t a) {
    asm volatile("ldmatrix.sync.aligned.m8n8.x4.shared.b16 {%0,%1,%2,%3}, [%4];"
                 : "=r"(r[0]), "=r"(r[1]), "=r"(r[2]), "=r"(r[3]) : "r"(a));
}
__device__ __forceinline__ void ldsm4t(uint32_t* r, uint32_t a) {
    asm volatile("ldmatrix.sync.aligned.m8n8.x4.trans.shared.b16 {%0,%1,%2,%3}, [%4];"
                 : "=r"(r[0]), "=r"(r[1]), "=r"(r[2]), "=r"(r[3]) : "r"(a));
}
__device__ __forceinline__ void cpa16(uint32_t dst, const void* src) {
    asm volatile("cp.async.cg.shared.global [%0], [%1], 16;" :: "r"(dst), "l"(src));
}
__device__ __forceinline__ void cpa_commit() {
    asm volatile("cp.async.commit_group;" ::: "memory");
}
template <int NWAIT>
__device__ __forceinline__ void cpa_wait() {
    asm volatile("cp.async.wait_group %0;" :: "n"(NWAIT) : "memory");
}

// ---------------- merged prep: gating + transposes + f2h -----------------------
#define GB   512                             // gating blocks (T_TOK/8)
#define TR1B 1728                            // sWi transpose (24 x 72)
#define TR2B 864                             // sWo transpose (36 x 24)
#define N8_X   ((long)T_TOK * H_DIM / 8)
#define N8_WI  ((long)E_NUM * H_DIM * TWO_I / 8)
#define N8_WO  ((long)E_NUM * I_DIM * H_DIM / 8)
#define N8_TOT (N8_X + N8_WI + N8_WO)        // 3,047,424 (divisible by 512)
#define F2HB   ((int)(N8_TOT / 512))         // 2 uint4 outputs per thread

__device__ __forceinline__ void f2h_one(const float* __restrict__ x,
                                        const float* __restrict__ wi,
                                        const float* __restrict__ wo, long i) {
    const float* src; __half* dst; long off;
    if (i < N8_X)              { src = x;  dst = g_hx;  off = i; }
    else if (i < N8_X + N8_WI) { src = wi; dst = g_hwi; off = i - N8_X; }
    else                       { src = wo; dst = g_hwo; off = i - N8_X - N8_WI; }
    const float4* s = (const float4*)src + off * 2;
    float4 a = s[0], b = s[1];
    __half2 h0 = __floats2half2_rn(a.x, a.y);
    __half2 h1 = __floats2half2_rn(a.z, a.w);
    __half2 h2 = __floats2half2_rn(b.x, b.y);
    __half2 h3 = __floats2half2_rn(b.z, b.w);
    uint4 v = { *(uint32_t*)&h0, *(uint32_t*)&h1, *(uint32_t*)&h2, *(uint32_t*)&h3 };
    ((uint4*)dst)[off] = v;
}

__global__ void __launch_bounds__(256)
prep_kernel(const float* __restrict__ x,   const float* __restrict__ gate_w,
            const float* __restrict__ bias, const float* __restrict__ wi,
            const float* __restrict__ wo,   const float* __restrict__ swi,
            const float* __restrict__ swo) {
    __shared__ float sbuf[E_NUM * H_DIM];    // 24 KB, reused by all branches
    int b = blockIdx.x;
    int tid = threadIdx.x;

    if (b < GB) {
        // ---------- gating ----------
        for (int i = tid; i < E_NUM * H_DIM; i += 256) sbuf[i] = gate_w[i];
        __syncthreads();

        int warp = tid >> 5, lane = tid & 31;
        int t = b * 8 + warp;
        const float* xr = x + (size_t)t * H_DIM;

        float acc[E_NUM];
#pragma unroll
        for (int e = 0; e < E_NUM; e++) acc[e] = 0.f;
        for (int h = lane; h < H_DIM; h += 32) {
            float xv = xr[h];
#pragma unroll
            for (int e = 0; e < E_NUM; e++) acc[e] += xv * sbuf[e * H_DIM + h];
        }
#pragma unroll
        for (int e = 0; e < E_NUM; e++) {
            float v = acc[e];
#pragma unroll
            for (int o = 16; o > 0; o >>= 1) v += __shfl_down_sync(0xffffffffu, v, o);
            acc[e] = v;
        }
        if (lane == 0) {
            float logit[E_NUM];
#pragma unroll
            for (int e = 0; e < E_NUM; e++) logit[e] = 1.f / (1.f + expf(-acc[e]));
            int i0 = 0; float b0 = -1e30f;
#pragma unroll
            for (int e = 0; e < E_NUM; e++) {
                float s = logit[e] + bias[e];
                if (s > b0) { b0 = s; i0 = e; }
            }
            int i1 = 0; float b1 = -1e30f;
#pragma unroll
            for (int e = 0; e < E_NUM; e++) {
                if (e == i0) continue;
                float s = logit[e] + bias[e];
                if (s > b1) { b1 = s; i1 = e; }
            }
            float w0 = logit[i0], w1 = logit[i1];
            float inv = 1.f / (w0 + w1);
            w0 *= inv; w1 *= inv;
            int p0 = atomicAdd(&g_count[i0], 1);
            g_tok[i0 * T_TOK + p0] = t; g_dst[i0 * T_TOK + p0] = 2 * t;     g_w[i0 * T_TOK + p0] = w0;
            int p1 = atomicAdd(&g_count[i1], 1);
            g_tok[i1 * T_TOK + p1] = t; g_dst[i1 * T_TOK + p1] = 2 * t + 1; g_w[i1 * T_TOK + p1] = w1;
        }
    } else if (b < GB + TR1B) {
        // ---------- sWi transpose: [2I][H] f32 -> [H][2I] f16 ----------
        float (*tile)[33] = (float (*)[33])sbuf;
        int bb = b - GB;
        int c0 = (bb % 24) * 32;   // H
        int r0 = (bb / 24) * 32;   // 2I
        int tx = tid & 31, ty = tid >> 5;
#pragma unroll
        for (int i = 0; i < 32; i += 8)
            tile[ty + i][tx] = swi[(size_t)(r0 + ty + i) * H_DIM + c0 + tx];
        __syncthreads();
#pragma unroll
        for (int i = 0; i < 32; i += 8)
            g_hswiT[(size_t)(c0 + ty + i) * TWO_I + r0 + tx] = __float2half(tile[tx][ty + i]);
    } else if (b < GB + TR1B + TR2B) {
        // ---------- sWo transpose: [H][I] f32 -> [I][H] f16 ----------
        float (*tile)[33] = (float (*)[33])sbuf;
        int bb = b - GB - TR1B;
        int c0 = (bb % 36) * 32;   // I (cols of src)
        int r0 = (bb / 36) * 32;   // H (rows of src)
        int tx = tid & 31, ty = tid >> 5;
#pragma unroll
        for (int i = 0; i < 32; i += 8)
            tile[ty + i][tx] = swo[(size_t)(r0 + ty + i) * I_DIM + c0 + tx];
        __syncthreads();
#pragma unroll
        for (int i = 0; i < 32; i += 8)
            g_hswoT[(size_t)(c0 + ty + i) * H_DIM + r0 + tx] = __float2half(tile[tx][ty + i]);
    } else {
        // ---------- f2h convert (x, Wi, Wo): 2 independent uint4s / thread ----
        long base = (long)(b - GB - TR1B - TR2B) * 512;
        f2h_one(x, wi, wo, base + tid);
        f2h_one(x, wi, wo, base + 256 + tid);
    }
}

// ================= UP GEMM (merged, z=9): Round-11 exact =======================
#define U_ASTR  80u
#define U_ATILE 10240u
#define U_BT    8704u
#define U_SSB   (U_ATILE + 2 * U_BT)

__global__ void __launch_bounds__(512, 1)
up_gemm(const __half* __restrict__ Xh, const __half* __restrict__ Wih,
        const __half* __restrict__ sWiTh) {
    constexpr int K = H_DIM, NC = K / 32;

    int e = blockIdx.z;
    bool sh = (e == 8);
    int cnt = sh ? T_TOK : g_count[e];
    int bm  = blockIdx.y * 128;
    if (bm >= cnt) return;
    int c0  = blockIdx.x * 128;

    extern __shared__ char smc[];
    uint32_t smaddr = (uint32_t)__cvta_generic_to_shared(smc);
    int tid = threadIdx.x;

    int am = tid >> 2, aseg = tid & 3;
    int apos = bm + am;
    long arow;
    if (sh) arow = apos;
    else    arow = g_tok[e * T_TOK + ((apos < cnt) ? apos : (cnt - 1))];
    const __half* aSrc = Xh + (size_t)arow * K + aseg * 8;
    uint32_t aDst = (uint32_t)am * U_ASTR + aseg * 16;

    const __half* Bbase = sh ? sWiTh : (Wih + (size_t)e * K * TWO_I);
    int kr = tid >> 4, n8 = tid & 15;
    const __half* bSrc0 = Bbase + (size_t)kr * TWO_I + c0 + n8 * 8;
    const __half* bSrc1 = bSrc0 + I_DIM;
    uint32_t bDst0 = U_ATILE + (uint32_t)kr * 272 + n8 * 16;
    uint32_t bDst1 = bDst0 + U_BT;

    float acc[2][8][4];
#pragma unroll
    for (int i = 0; i < 2; i++)
#pragma unroll
        for (int j = 0; j < 8; j++)
#pragma unroll
            for (int q = 0; q < 4; q++) acc[i][j][q] = 0.f;

#pragma unroll
    for (int s = 0; s < 2; s++) {
        uint32_t base = smaddr + s * U_SSB;
        cpa16(base + aDst, aSrc + s * 32);
        cpa16(base + bDst0, bSrc0 + (size_t)s * 32 * TWO_I);
        cpa16(base + bDst1, bSrc1 + (size_t)s * 32 * TWO_I);
        cpa_commit();
    }

    int warp = tid >> 5, lane = tid & 31;
    int wm = warp >> 2, wn = warp & 3;

    uint32_t aLd = (uint32_t)(wm * 32 + (lane & 15)) * U_ASTR + (lane >> 4) * 16;
    uint32_t bLd = U_ATILE + (uint32_t)(lane & 15) * 272 + (wn * 4 + (lane >> 4)) * 16;

    for (int c = 0; c < NC; c++) {
        cpa_wait<1>();
        __syncthreads();

        int pf = c + 2;
        if (pf < NC) {
            uint32_t base = smaddr + (uint32_t)(pf % 3) * U_SSB;
            cpa16(base + aDst, aSrc + pf * 32);
            cpa16(base + bDst0, bSrc0 + (size_t)pf * 32 * TWO_I);
            cpa16(base + bDst1, bSrc1 + (size_t)pf * 32 * TWO_I);
        }
        cpa_commit();

        uint32_t sbase = smaddr + (uint32_t)(c % 3) * U_SSB;
#pragma unroll
        for (int ks = 0; ks < 2; ks++) {
            uint32_t af[2][4], bf[2][2][4];
#pragma unroll
            for (int mi = 0; mi < 2; mi++)
                ldsm4(af[mi], sbase + aLd + mi * (16 * U_ASTR) + ks * 32);
#pragma unroll
            for (int t = 0; t < 2; t++)
#pragma unroll
                for (int p = 0; p < 2; p++)
                    ldsm4t(bf[t][p], sbase + bLd + t * U_BT + p * 32 +
                           (uint32_t)ks * (16 * 272));
#pragma unroll
            for (int mi = 0; mi < 2; mi++)
#pragma unroll
                for (int t = 0; t < 2; t++)
#pragma unroll
                    for (int p = 0; p < 2; p++)
#pragma unroll
                        for (int j = 0; j < 2; j++) {
                            uint32_t b2[2] = { bf[t][p][j * 2], bf[t][p][j * 2 + 1] };
                            mma16(acc[mi][t * 4 + p * 2 + j], af[mi], b2);
                        }
        }
    }

    int g = lane >> 2, q = lane & 3;
#pragma unroll
    for (int mi = 0; mi < 2; mi++) {
        int r0 = bm + wm * 32 + mi * 16 + g;
        int r1 = r0 + 8;
        long o0 = -1, o1 = -1;
        float w0 = 1.f, w1 = 1.f;
        __half* C;
        if (sh) {
            C = g_as; o0 = r0; o1 = r1;
        } else {
            C = g_act;
            if (r0 < cnt) { o0 = (long)e * T_TOK + r0; w0 = g_w[e * T_TOK + r0]; }
            if (r1 < cnt) { o1 = (long)e * T_TOK + r1; w1 = g_w[e * T_TOK + r1]; }
        }
#pragma unroll
        for (int nidx = 0; nidx < 4; nidx++) {
            int col = c0 + wn * 32 + (nidx >> 1) * 16 + (nidx & 1) * 8 + 2 * q;
            float p0 = acc[mi][nidx][0],     p1 = acc[mi][nidx][1];
            float p2 = acc[mi][nidx][2],     p3 = acc[mi][nidx][3];
            float g0 = acc[mi][4 + nidx][0], g1 = acc[mi][4 + nidx][1];
            float g2 = acc[mi][4 + nidx][2], g3 = acc[mi][4 + nidx][3];
            if (o0 >= 0) {
                float v0 = sh ? silu_f(p0) * g0 : silu_f(g0) * p0 * w0;
                float v1 = sh ? silu_f(p1) * g1 : silu_f(g1) * p1 * w0;
                *(__half2*)&C[o0 * I_DIM + col] = __floats2half2_rn(v0, v1);
            }
            if (o1 >= 0) {
                float v0 = sh ? silu_f(p2) * g2 : silu_f(g2) * p2 * w1;
                float v1 = sh ? silu_f(p3) * g3 : silu_f(g3) * p3 * w1;
                *(__half2*)&C[o1 * I_DIM + col] = __floats2half2_rn(v0, v1);
            }
        }
    }
}

// ================= DOWN GEMM (merged, z=9): Round-11 exact =====================
#define D_ASTR  80u
#define D_ATILE 10240u
#define D_BSTR  528u
#define D_BT    (32u * D_BSTR)      // 16896
#define D_SSB   (D_ATILE + D_BT)    // 27136

__global__ void __launch_bounds__(512, 1)
down_gemm(const __half* __restrict__ Acth, const __half* __restrict__ Ash,
          const __half* __restrict__ Woh,  const __half* __restrict__ sWoTh,
          float* __restrict__ Par, float* __restrict__ Out) {
    constexpr int N = H_DIM, K = I_DIM, NC = K / 32;

    int e = blockIdx.z;
    bool sh = (e == 8);
    int cnt = sh ? T_TOK : g_count[e];
    int bm  = blockIdx.y * 128;
    if (bm >= cnt) return;
    int bn  = blockIdx.x * 256;

    extern __shared__ char smc[];
    uint32_t smaddr = (uint32_t)__cvta_generic_to_shared(smc);
    int tid = threadIdx.x;

    int am = tid >> 2, aseg = tid & 3;
    int apos = bm + am;
    long arow = sh ? apos : ((long)e * T_TOK + ((apos < cnt) ? apos : 0));
    const __half* Abase = sh ? Ash : Acth;
    const __half* aSrc = Abase + (size_t)arow * K + aseg * 8;
    uint32_t aDst = (uint32_t)am * D_ASTR + aseg * 16;

    const __half* Bbase = sh ? sWoTh : (Woh + (size_t)e * K * N);
    int kr = tid >> 4, bs = tid & 15;
    const __half* bSrc = Bbase + (size_t)kr * N + bn + bs * 16;
    uint32_t bDst = D_ATILE + (uint32_t)kr * D_BSTR + bs * 32;

    float acc[2][8][4];
#pragma unroll
    for (int i = 0; i < 2; i++)
#pragma unroll
        for (int j = 0; j < 8; j++)
#pragma unroll
            for (int q = 0; q < 4; q++) acc[i][j][q] = 0.f;

#pragma unroll
    for (int s = 0; s < 2; s++) {
        uint32_t base = smaddr + s * D_SSB;
        cpa16(base + aDst, aSrc + s * 32);
        cpa16(base + bDst,      bSrc + (size_t)s * 32 * N);
        cpa16(base + bDst + 16, bSrc + (size_t)s * 32 * N + 8);
        cpa_commit();
    }

    int warp = tid >> 5, lane = tid & 31;
    int wm = warp >> 2, wn = warp & 3;

    uint32_t aLd = (uint32_t)(wm * 32 + (lane & 15)) * D_ASTR + (lane >> 4) * 16;
    uint32_t bLd = D_ATILE + (uint32_t)(lane & 15) * D_BSTR + (wn * 8 + (lane >> 4)) * 16;

    for (int c = 0; c < NC; c++) {
        cpa_wait<1>();
        __syncthreads();

        int pf = c + 2;
        if (pf < NC) {
            uint32_t base = smaddr + (uint32_t)(pf % 3) * D_SSB;
            cpa16(base + aDst, aSrc + pf * 32);
            cpa16(base + bDst,      bSrc + (size_t)pf * 32 * N);
            cpa16(base + bDst + 16, bSrc + (size_t)pf * 32 * N + 8);
        }
        cpa_commit();

        uint32_t sbase = smaddr + (uint32_t)(c % 3) * D_SSB;
#pragma unroll
        for (int ks = 0; ks < 2; ks++) {
            uint32_t af[2][4], bf[4][4];
#pragma unroll
            for (int mi = 0; mi < 2; mi++)
                ldsm4(af[mi], sbase + aLd + mi * (16 * D_ASTR) + ks * 32);
#pragma unroll
            for (int p = 0; p < 4; p++)
                ldsm4t(bf[p], sbase + bLd + p * 32 + (uint32_t)ks * (16 * D_BSTR));
#pragma unroll
            for (int mi = 0; mi < 2; mi++)
#pragma unroll
                for (int p = 0; p < 4; p++)
#pragma unroll
                    for (int j = 0; j < 2; j++) {
                        uint32_t b2[2] = { bf[p][j * 2], bf[p][j * 2 + 1] };
                        mma16(acc[mi][p * 2 + j], af[mi], b2);
                    }
        }
    }

    int g = lane >> 2, q = lane & 3;
#pragma unroll
    for (int mi = 0; mi < 2; mi++) {
        int r0 = bm + wm * 32 + mi * 16 + g;
        int r1 = r0 + 8;
        if (sh) {
#pragma unroll
            for (int ni = 0; ni < 8; ni++) {
                int cx = bn + wn * 64 + ni * 8 + 2 * q;
                float2 v0 = { acc[mi][ni][0], acc[mi][ni][1] };
                float2 v1 = { acc[mi][ni][2], acc[mi][ni][3] };
                *(float2*)&Out[(size_t)r0 * H_DIM + cx] = v0;
                *(float2*)&Out[(size_t)r1 * H_DIM + cx] = v1;
            }
        } else {
            long o0 = (r0 < cnt) ? (long)g_dst[e * T_TOK + r0] : -1;
            long o1 = (r1 < cnt) ? (long)g_dst[e * T_TOK + r1] : -1;
#pragma unroll
            for (int ni = 0; ni < 8; ni++) {
                int cx = bn + wn * 64 + ni * 8 + 2 * q;
                if (o0 >= 0) {
                    float2 v = { acc[mi][ni][0], acc[mi][ni][1] };
                    *(float2*)&Par[o0 * H_DIM + cx] = v;
                }
                if (o1 >= 0) {
                    float2 v = { acc[mi][ni][2], acc[mi][ni][3] };
                    *(float2*)&Par[o1 * H_DIM + cx] = v;
                }
            }
        }
    }
}

// ---------------- final add: 8 floats/thread (+ counter reset) -----------------
__global__ void __launch_bounds__(256)
final_add_kernel(float* __restrict__ out) {
    int idx8 = blockIdx.x * 256 + threadIdx.x;   // over T*H/8
    if (blockIdx.x == 0 && threadIdx.x < E_NUM) g_count[threadIdx.x] = 0;
    int h8 = idx8 % (H_DIM / 8);
    int t  = idx8 / (H_DIM / 8);
    const float4* par = (const float4*)g_par;
    float4* o4 = (float4*)out + (size_t)idx8 * 2;
    float4 oa = o4[0], ob = o4[1];
    const float4* pr0 = par + (size_t)(2 * t) * (H_DIM / 4) + h8 * 2;
    const float4* pr1 = par + (size_t)(2 * t + 1) * (H_DIM / 4) + h8 * 2;
    float4 p0a = pr0[0], p0b = pr0[1];
    float4 p1a = pr1[0], p1b = pr1[1];
    oa.x += p0a.x + p1a.x; oa.y += p0a.y + p1a.y;
    oa.z += p0a.z + p1a.z; oa.w += p0a.w + p1a.w;
    ob.x += p0b.x + p1b.x; ob.y += p0b.y + p1b.y;
    ob.z += p0b.z + p1b.z; ob.w += p0b.w + p1b.w;
    o4[0] = oa; o4[1] = ob;
}

// ---------------- launch ---------------------------------------------------------
extern "C" void kernel_launch(void* const* d_in, const int* in_sizes, int n_in,
                              void* d_out, int out_size) {
    const float* x      = (const float*)d_in[0];
    const float* gate_w = (const float*)d_in[1];
    const float* bias   = (const float*)d_in[2];
    const float* Wi     = (const float*)d_in[3];
    const float* Wo     = (const float*)d_in[4];
    const float* sWi    = (const float*)d_in[5];
    const float* sWo    = (const float*)d_in[6];
    float* out = (float*)d_out;

    __half *p_act, *p_as, *p_hx, *p_hwi, *p_hwo, *p_hswiT, *p_hswoT;
    float* p_par;
    cudaGetSymbolAddress((void**)&p_act,   g_act);
    cudaGetSymbolAddress((void**)&p_as,    g_as);
    cudaGetSymbolAddress((void**)&p_par,   g_par);
    cudaGetSymbolAddress((void**)&p_hx,    g_hx);
    cudaGetSymbolAddress((void**)&p_hwi,   g_hwi);
    cudaGetSymbolAddress((void**)&p_hwo,   g_hwo);
    cudaGetSymbolAddress((void**)&p_hswiT, g_hswiT);
    cudaGetSymbolAddress((void**)&p_hswoT, g_hswoT);

    const int SMEM_UP = 3 * U_SSB;   // 82944
    const int SMEM_DN = 3 * D_SSB;   // 81408

    cudaFuncSetAttribute(up_gemm,   cudaFuncAttributeMaxDynamicSharedMemorySize, SMEM_UP);
    cudaFuncSetAttribute(down_gemm, cudaFuncAttributeMaxDynamicSharedMemorySize, SMEM_DN);

    // merged prep: gating + sWi/sWo transposes + f2h (2 uint4/thread), one launch
    prep_kernel<<<GB + TR1B + TR2B + F2HB, 256>>>(x, gate_w, bias, Wi, Wo, sWi, sWo);

    // merged up: z<8 experts -> g_act, z=8 shared -> g_as
    up_gemm<<<dim3(I_DIM / 128, T_TOK / 128, 9), 512, SMEM_UP>>>(p_hx, p_hwi, p_hswiT);

    // merged down (NN-only): z<8 expert scatter -> g_par, z=8 shared -> out
    down_gemm<<<dim3(H_DIM / 256, T_TOK / 128, 9), 512, SMEM_DN>>>(
        p_act, p_as, p_hwo, p_hswoT, p_par, out);

    // out += par pairs (8 floats/thread); re-zeroes g_count for next replay
    final_add_kernel<<<(T_TOK * H_DIM / 8) / 256, 256>>>(out);
}

// round 15
// speedup vs baseline: 1.0142x; 1.0142x over previous
#include <cuda_runtime.h>
#include <cuda_fp16.h>
#include <math.h>
#include <stdint.h>

#define T_TOK 4096
#define H_DIM 768
#define I_DIM 1152
#define TWO_I 2304
#define E_NUM 8

// ---------------- device-global scratch ------------------------------------
__device__ int    g_count[E_NUM];               // zero-init; re-zeroed by final_add
__device__ int    g_tok[E_NUM * T_TOK];
__device__ int    g_dst[E_NUM * T_TOK];
__device__ float  g_w  [E_NUM * T_TOK];
__device__ __half g_act[(size_t)E_NUM * T_TOK * I_DIM];  // expert GLU out
__device__ __half g_as [(size_t)T_TOK * I_DIM];          // shared GLU out
__device__ __half g_par[(size_t)T_TOK * 2 * H_DIM];      // per-(t,k) down-proj (fp16)
__device__ __half g_hx   [(size_t)T_TOK * H_DIM];        // x fp16
__device__ __half g_hwi  [(size_t)E_NUM * H_DIM * TWO_I];// Wi fp16 [K][2I]
__device__ __half g_hwo  [(size_t)E_NUM * I_DIM * H_DIM];// Wo fp16 [K][N]
__device__ __half g_hswiT[(size_t)H_DIM * TWO_I];        // sWi^T fp16 [K][2I]
__device__ __half g_hswoT[(size_t)I_DIM * H_DIM];        // sWo^T fp16 [K][N]

// ---------------- PTX helpers ------------------------------------------------
__device__ __forceinline__ float silu_f(float v) { return v / (1.f + __expf(-v)); }

__device__ __forceinline__ void mma16(float* c, const uint32_t* a, const uint32_t* b) {
    asm volatile(
        "mma.sync.aligned.m16n8k16.row.col.f32.f16.f16.f32 "
        "{%0,%1,%2,%3},{%4,%5,%6,%7},{%8,%9},{%0,%1,%2,%3};"
        : "+f"(c[0]), "+f"(c[1]), "+f"(c[2]), "+f"(c[3])
        : "r"(a[0]), "r"(a[1]), "r"(a[2]), "r"(a[3]), "r"(b[0]), "r"(b[1]));
}
__device__ __forceinline__ void ldsm4(uint32_t* r, uint32_t a) {
    asm volatile("ldmatrix.sync.aligned.m8n8.x4.shared.b16 {%0,%1,%2,%3}, [%4];"
                 : "=r"(r[0]), "=r"(r[1]), "=r"(r[2]), "=r"(r[3]) : "r"(a));
}
__device__ __forceinline__ void ldsm4t(uint32_t* r, uint32_t a) {
    asm volatile("ldmatrix.sync.aligned.m8n8.x4.trans.shared.b16 {%0,%1,%2,%3}, [%4];"
                 : "=r"(r[0]), "=r"(r[1]), "=r"(r[2]), "=r"(r[3]) : "r"(a));
}
__device__ __forceinline__ void cpa16(uint32_t dst, const void* src) {
    asm volatile("cp.async.cg.shared.global [%0], [%1], 16;" :: "r"(dst), "l"(src));
}
__device__ __forceinline__ void cpa_commit() {
    asm volatile("cp.async.commit_group;" ::: "memory");
}
template <int NWAIT>
__device__ __forceinline__ void cpa_wait() {
    asm volatile("cp.async.wait_group %0;" :: "n"(NWAIT) : "memory");
}

// ---------------- merged prep: gating + transposes + f2h -----------------------
#define GB   512                             // gating blocks (T_TOK/8)
#define TR1B 1728                            // sWi transpose (24 x 72)
#define TR2B 864                             // sWo transpose (36 x 24)
#define N8_X   ((long)T_TOK * H_DIM / 8)
#define N8_WI  ((long)E_NUM * H_DIM * TWO_I / 8)
#define N8_WO  ((long)E_NUM * I_DIM * H_DIM / 8)
#define N8_TOT (N8_X + N8_WI + N8_WO)
#define F2HB   ((int)((N8_TOT + 255) / 256))

__global__ void __launch_bounds__(256)
prep_kernel(const float* __restrict__ x,   const float* __restrict__ gate_w,
            const float* __restrict__ bias, const float* __restrict__ wi,
            const float* __restrict__ wo,   const float* __restrict__ swi,
            const float* __restrict__ swo) {
    __shared__ float sbuf[E_NUM * H_DIM];    // 24 KB, reused by all branches
    int b = blockIdx.x;
    int tid = threadIdx.x;

    if (b < GB) {
        // ---------- gating ----------
        for (int i = tid; i < E_NUM * H_DIM; i += 256) sbuf[i] = gate_w[i];
        __syncthreads();

        int warp = tid >> 5, lane = tid & 31;
        int t = b * 8 + warp;
        const float* xr = x + (size_t)t * H_DIM;

        float acc[E_NUM];
#pragma unroll
        for (int e = 0; e < E_NUM; e++) acc[e] = 0.f;
        for (int h = lane; h < H_DIM; h += 32) {
            float xv = xr[h];
#pragma unroll
            for (int e = 0; e < E_NUM; e++) acc[e] += xv * sbuf[e * H_DIM + h];
        }
#pragma unroll
        for (int e = 0; e < E_NUM; e++) {
            float v = acc[e];
#pragma unroll
            for (int o = 16; o > 0; o >>= 1) v += __shfl_down_sync(0xffffffffu, v, o);
            acc[e] = v;
        }
        if (lane == 0) {
            float logit[E_NUM];
#pragma unroll
            for (int e = 0; e < E_NUM; e++) logit[e] = 1.f / (1.f + expf(-acc[e]));
            int i0 = 0; float b0 = -1e30f;
#pragma unroll
            for (int e = 0; e < E_NUM; e++) {
                float s = logit[e] + bias[e];
                if (s > b0) { b0 = s; i0 = e; }
            }
            int i1 = 0; float b1 = -1e30f;
#pragma unroll
            for (int e = 0; e < E_NUM; e++) {
                if (e == i0) continue;
                float s = logit[e] + bias[e];
                if (s > b1) { b1 = s; i1 = e; }
            }
            float w0 = logit[i0], w1 = logit[i1];
            float inv = 1.f / (w0 + w1);
            w0 *= inv; w1 *= inv;
            int p0 = atomicAdd(&g_count[i0], 1);
            g_tok[i0 * T_TOK + p0] = t; g_dst[i0 * T_TOK + p0] = 2 * t;     g_w[i0 * T_TOK + p0] = w0;
            int p1 = atomicAdd(&g_count[i1], 1);
            g_tok[i1 * T_TOK + p1] = t; g_dst[i1 * T_TOK + p1] = 2 * t + 1; g_w[i1 * T_TOK + p1] = w1;
        }
    } else if (b < GB + TR1B) {
        // ---------- sWi transpose: [2I][H] f32 -> [H][2I] f16 ----------
        float (*tile)[33] = (float (*)[33])sbuf;
        int bb = b - GB;
        int c0 = (bb % 24) * 32;   // H
        int r0 = (bb / 24) * 32;   // 2I
        int tx = tid & 31, ty = tid >> 5;
#pragma unroll
        for (int i = 0; i < 32; i += 8)
            tile[ty + i][tx] = swi[(size_t)(r0 + ty + i) * H_DIM + c0 + tx];
        __syncthreads();
#pragma unroll
        for (int i = 0; i < 32; i += 8)
            g_hswiT[(size_t)(c0 + ty + i) * TWO_I + r0 + tx] = __float2half(tile[tx][ty + i]);
    } else if (b < GB + TR1B + TR2B) {
        // ---------- sWo transpose: [H][I] f32 -> [I][H] f16 ----------
        float (*tile)[33] = (float (*)[33])sbuf;
        int bb = b - GB - TR1B;
        int c0 = (bb % 36) * 32;   // I (cols of src)
        int r0 = (bb / 36) * 32;   // H (rows of src)
        int tx = tid & 31, ty = tid >> 5;
#pragma unroll
        for (int i = 0; i < 32; i += 8)
            tile[ty + i][tx] = swo[(size_t)(r0 + ty + i) * I_DIM + c0 + tx];
        __syncthreads();
#pragma unroll
        for (int i = 0; i < 32; i += 8)
            g_hswoT[(size_t)(c0 + ty + i) * H_DIM + r0 + tx] = __float2half(tile[tx][ty + i]);
    } else {
        // ---------- f2h convert (x, Wi, Wo) ----------
        long i = (long)(b - GB - TR1B - TR2B) * 256 + tid;
        if (i >= N8_TOT) return;
        const float* src; __half* dst; long off;
        if (i < N8_X)              { src = x;  dst = g_hx;  off = i; }
        else if (i < N8_X + N8_WI) { src = wi; dst = g_hwi; off = i - N8_X; }
        else                       { src = wo; dst = g_hwo; off = i - N8_X - N8_WI; }
        const float4* s = (const float4*)src + off * 2;
        float4 a = s[0], bb4 = s[1];
        __half2 h0 = __floats2half2_rn(a.x, a.y);
        __half2 h1 = __floats2half2_rn(a.z, a.w);
        __half2 h2 = __floats2half2_rn(bb4.x, bb4.y);
        __half2 h3 = __floats2half2_rn(bb4.z, bb4.w);
        uint4 v = { *(uint32_t*)&h0, *(uint32_t*)&h1, *(uint32_t*)&h2, *(uint32_t*)&h3 };
        ((uint4*)dst)[off] = v;
    }
}

// ================= UP GEMM (merged, z=9): Round-11 exact =======================
#define U_ASTR  80u
#define U_ATILE 10240u
#define U_BT    8704u
#define U_SSB   (U_ATILE + 2 * U_BT)

__global__ void __launch_bounds__(512, 1)
up_gemm(const __half* __restrict__ Xh, const __half* __restrict__ Wih,
        const __half* __restrict__ sWiTh) {
    constexpr int K = H_DIM, NC = K / 32;

    int e = blockIdx.z;
    bool sh = (e == 8);
    int cnt = sh ? T_TOK : g_count[e];
    int bm  = blockIdx.y * 128;
    if (bm >= cnt) return;
    int c0  = blockIdx.x * 128;

    extern __shared__ char smc[];
    uint32_t smaddr = (uint32_t)__cvta_generic_to_shared(smc);
    int tid = threadIdx.x;

    int am = tid >> 2, aseg = tid & 3;
    int apos = bm + am;
    long arow;
    if (sh) arow = apos;
    else    arow = g_tok[e * T_TOK + ((apos < cnt) ? apos : (cnt - 1))];
    const __half* aSrc = Xh + (size_t)arow * K + aseg * 8;
    uint32_t aDst = (uint32_t)am * U_ASTR + aseg * 16;

    const __half* Bbase = sh ? sWiTh : (Wih + (size_t)e * K * TWO_I);
    int kr = tid >> 4, n8 = tid & 15;
    const __half* bSrc0 = Bbase + (size_t)kr * TWO_I + c0 + n8 * 8;
    const __half* bSrc1 = bSrc0 + I_DIM;
    uint32_t bDst0 = U_ATILE + (uint32_t)kr * 272 + n8 * 16;
    uint32_t bDst1 = bDst0 + U_BT;

    float acc[2][8][4];
#pragma unroll
    for (int i = 0; i < 2; i++)
#pragma unroll
        for (int j = 0; j < 8; j++)
#pragma unroll
            for (int q = 0; q < 4; q++) acc[i][j][q] = 0.f;

#pragma unroll
    for (int s = 0; s < 2; s++) {
        uint32_t base = smaddr + s * U_SSB;
        cpa16(base + aDst, aSrc + s * 32);
        cpa16(base + bDst0, bSrc0 + (size_t)s * 32 * TWO_I);
        cpa16(base + bDst1, bSrc1 + (size_t)s * 32 * TWO_I);
        cpa_commit();
    }

    int warp = tid >> 5, lane = tid & 31;
    int wm = warp >> 2, wn = warp & 3;

    uint32_t aLd = (uint32_t)(wm * 32 + (lane & 15)) * U_ASTR + (lane >> 4) * 16;
    uint32_t bLd = U_ATILE + (uint32_t)(lane & 15) * 272 + (wn * 4 + (lane >> 4)) * 16;

    for (int c = 0; c < NC; c++) {
        cpa_wait<1>();
        __syncthreads();

        int pf = c + 2;
        if (pf < NC) {
            uint32_t base = smaddr + (uint32_t)(pf % 3) * U_SSB;
            cpa16(base + aDst, aSrc + pf * 32);
            cpa16(base + bDst0, bSrc0 + (size_t)pf * 32 * TWO_I);
            cpa16(base + bDst1, bSrc1 + (size_t)pf * 32 * TWO_I);
        }
        cpa_commit();

        uint32_t sbase = smaddr + (uint32_t)(c % 3) * U_SSB;
#pragma unroll
        for (int ks = 0; ks < 2; ks++) {
            uint32_t af[2][4], bf[2][2][4];
#pragma unroll
            for (int mi = 0; mi < 2; mi++)
                ldsm4(af[mi], sbase + aLd + mi * (16 * U_ASTR) + ks * 32);
#pragma unroll
            for (int t = 0; t < 2; t++)
#pragma unroll
                for (int p = 0; p < 2; p++)
                    ldsm4t(bf[t][p], sbase + bLd + t * U_BT + p * 32 +
                           (uint32_t)ks * (16 * 272));
#pragma unroll
            for (int mi = 0; mi < 2; mi++)
#pragma unroll
                for (int t = 0; t < 2; t++)
#pragma unroll
                    for (int p = 0; p < 2; p++)
#pragma unroll
                        for (int j = 0; j < 2; j++) {
                            uint32_t b2[2] = { bf[t][p][j * 2], bf[t][p][j * 2 + 1] };
                            mma16(acc[mi][t * 4 + p * 2 + j], af[mi], b2);
                        }
        }
    }

    int g = lane >> 2, q = lane & 3;
#pragma unroll
    for (int mi = 0; mi < 2; mi++) {
        int r0 = bm + wm * 32 + mi * 16 + g;
        int r1 = r0 + 8;
        long o0 = -1, o1 = -1;
        float w0 = 1.f, w1 = 1.f;
        __half* C;
        if (sh) {
            C = g_as; o0 = r0; o1 = r1;
        } else {
            C = g_act;
            if (r0 < cnt) { o0 = (long)e * T_TOK + r0; w0 = g_w[e * T_TOK + r0]; }
            if (r1 < cnt) { o1 = (long)e * T_TOK + r1; w1 = g_w[e * T_TOK + r1]; }
        }
#pragma unroll
        for (int nidx = 0; nidx < 4; nidx++) {
            int col = c0 + wn * 32 + (nidx >> 1) * 16 + (nidx & 1) * 8 + 2 * q;
            float p0 = acc[mi][nidx][0],     p1 = acc[mi][nidx][1];
            float p2 = acc[mi][nidx][2],     p3 = acc[mi][nidx][3];
            float g0 = acc[mi][4 + nidx][0], g1 = acc[mi][4 + nidx][1];
            float g2 = acc[mi][4 + nidx][2], g3 = acc[mi][4 + nidx][3];
            if (o0 >= 0) {
                float v0 = sh ? silu_f(p0) * g0 : silu_f(g0) * p0 * w0;
                float v1 = sh ? silu_f(p1) * g1 : silu_f(g1) * p1 * w0;
                *(__half2*)&C[o0 * I_DIM + col] = __floats2half2_rn(v0, v1);
            }
            if (o1 >= 0) {
                float v0 = sh ? silu_f(p2) * g2 : silu_f(g2) * p2 * w1;
                float v1 = sh ? silu_f(p3) * g3 : silu_f(g3) * p3 * w1;
                *(__half2*)&C[o1 * I_DIM + col] = __floats2half2_rn(v0, v1);
            }
        }
    }
}

// ================= DOWN GEMM (merged, z=9): Round-11 core, fp16 par ============
#define D_ASTR  80u
#define D_ATILE 10240u
#define D_BSTR  528u
#define D_BT    (32u * D_BSTR)      // 16896
#define D_SSB   (D_ATILE + D_BT)    // 27136

__global__ void __launch_bounds__(512, 1)
down_gemm(const __half* __restrict__ Acth, const __half* __restrict__ Ash,
          const __half* __restrict__ Woh,  const __half* __restrict__ sWoTh,
          __half* __restrict__ Par, float* __restrict__ Out) {
    constexpr int N = H_DIM, K = I_DIM, NC = K / 32;

    int e = blockIdx.z;
    bool sh = (e == 8);
    int cnt = sh ? T_TOK : g_count[e];
    int bm  = blockIdx.y * 128;
    if (bm >= cnt) return;
    int bn  = blockIdx.x * 256;

    extern __shared__ char smc[];
    uint32_t smaddr = (uint32_t)__cvta_generic_to_shared(smc);
    int tid = threadIdx.x;

    int am = tid >> 2, aseg = tid & 3;
    int apos = bm + am;
    long arow = sh ? apos : ((long)e * T_TOK + ((apos < cnt) ? apos : 0));
    const __half* Abase = sh ? Ash : Acth;
    const __half* aSrc = Abase + (size_t)arow * K + aseg * 8;
    uint32_t aDst = (uint32_t)am * D_ASTR + aseg * 16;

    const __half* Bbase = sh ? sWoTh : (Woh + (size_t)e * K * N);
    int kr = tid >> 4, bs = tid & 15;
    const __half* bSrc = Bbase + (size_t)kr * N + bn + bs * 16;
    uint32_t bDst = D_ATILE + (uint32_t)kr * D_BSTR + bs * 32;

    float acc[2][8][4];
#pragma unroll
    for (int i = 0; i < 2; i++)
#pragma unroll
        for (int j = 0; j < 8; j++)
#pragma unroll
            for (int q = 0; q < 4; q++) acc[i][j][q] = 0.f;

#pragma unroll
    for (int s = 0; s < 2; s++) {
        uint32_t base = smaddr + s * D_SSB;
        cpa16(base + aDst, aSrc + s * 32);
        cpa16(base + bDst,      bSrc + (size_t)s * 32 * N);
        cpa16(base + bDst + 16, bSrc + (size_t)s * 32 * N + 8);
        cpa_commit();
    }

    int warp = tid >> 5, lane = tid & 31;
    int wm = warp >> 2, wn = warp & 3;

    uint32_t aLd = (uint32_t)(wm * 32 + (lane & 15)) * D_ASTR + (lane >> 4) * 16;
    uint32_t bLd = D_ATILE + (uint32_t)(lane & 15) * D_BSTR + (wn * 8 + (lane >> 4)) * 16;

    for (int c = 0; c < NC; c++) {
        cpa_wait<1>();
        __syncthreads();

        int pf = c + 2;
        if (pf < NC) {
            uint32_t base = smaddr + (uint32_t)(pf % 3) * D_SSB;
            cpa16(base + aDst, aSrc + pf * 32);
            cpa16(base + bDst,      bSrc + (size_t)pf * 32 * N);
            cpa16(base + bDst + 16, bSrc + (size_t)pf * 32 * N + 8);
        }
        cpa_commit();

        uint32_t sbase = smaddr + (uint32_t)(c % 3) * D_SSB;
#pragma unroll
        for (int ks = 0; ks < 2; ks++) {
            uint32_t af[2][4], bf[4][4];
#pragma unroll
            for (int mi = 0; mi < 2; mi++)
                ldsm4(af[mi], sbase + aLd + mi * (16 * D_ASTR) + ks * 32);
#pragma unroll
            for (int p = 0; p < 4; p++)
                ldsm4t(bf[p], sbase + bLd + p * 32 + (uint32_t)ks * (16 * D_BSTR));
#pragma unroll
            for (int mi = 0; mi < 2; mi++)
#pragma unroll
                for (int p = 0; p < 4; p++)
#pragma unroll
                    for (int j = 0; j < 2; j++) {
                        uint32_t b2[2] = { bf[p][j * 2], bf[p][j * 2 + 1] };
                        mma16(acc[mi][p * 2 + j], af[mi], b2);
                    }
        }
    }

    int g = lane >> 2, q = lane & 3;
#pragma unroll
    for (int mi = 0; mi < 2; mi++) {
        int r0 = bm + wm * 32 + mi * 16 + g;
        int r1 = r0 + 8;
        if (sh) {
#pragma unroll
            for (int ni = 0; ni < 8; ni++) {
                int cx = bn + wn * 64 + ni * 8 + 2 * q;
                float2 v0 = { acc[mi][ni][0], acc[mi][ni][1] };
                float2 v1 = { acc[mi][ni][2], acc[mi][ni][3] };
                *(float2*)&Out[(size_t)r0 * H_DIM + cx] = v0;
                *(float2*)&Out[(size_t)r1 * H_DIM + cx] = v1;
            }
        } else {
            long o0 = (r0 < cnt) ? (long)g_dst[e * T_TOK + r0] : -1;
            long o1 = (r1 < cnt) ? (long)g_dst[e * T_TOK + r1] : -1;
#pragma unroll
            for (int ni = 0; ni < 8; ni++) {
                int cx = bn + wn * 64 + ni * 8 + 2 * q;
                if (o0 >= 0)
                    *(__half2*)&Par[o0 * H_DIM + cx] =
                        __floats2half2_rn(acc[mi][ni][0], acc[mi][ni][1]);
                if (o1 >= 0)
                    *(__half2*)&Par[o1 * H_DIM + cx] =
                        __floats2half2_rn(acc[mi][ni][2], acc[mi][ni][3]);
            }
        }
    }
}

// ---------------- final add: out += par[2t] + par[2t+1] (fp16 par) -------------
__global__ void __launch_bounds__(256)
final_add_kernel(float* __restrict__ out) {
    int idx4 = blockIdx.x * 256 + threadIdx.x;   // over T*H/4
    if (blockIdx.x == 0 && threadIdx.x < E_NUM) g_count[threadIdx.x] = 0;
    int h4 = idx4 % (H_DIM / 4);
    int t  = idx4 / (H_DIM / 4);
    float4 o = ((float4*)out)[idx4];
    const uint2 a0 = *(const uint2*)(g_par + (size_t)(2 * t) * H_DIM + h4 * 4);
    const uint2 a1 = *(const uint2*)(g_par + (size_t)(2 * t + 1) * H_DIM + h4 * 4);
    __half2 p00 = *(__half2*)&a0.x, p01 = *(__half2*)&a0.y;
    __half2 p10 = *(__half2*)&a1.x, p11 = *(__half2*)&a1.y;
    float2 f00 = __half22float2(p00), f01 = __half22float2(p01);
    float2 f10 = __half22float2(p10), f11 = __half22float2(p11);
    o.x += f00.x + f10.x;
    o.y += f00.y + f10.y;
    o.z += f01.x + f11.x;
    o.w += f01.y + f11.y;
    ((float4*)out)[idx4] = o;
}

// ---------------- launch ---------------------------------------------------------
extern "C" void kernel_launch(void* const* d_in, const int* in_sizes, int n_in,
                              void* d_out, int out_size) {
    const float* x      = (const float*)d_in[0];
    const float* gate_w = (const float*)d_in[1];
    const float* bias   = (const float*)d_in[2];
    const float* Wi     = (const float*)d_in[3];
    const float* Wo     = (const float*)d_in[4];
    const float* sWi    = (const float*)d_in[5];
    const float* sWo    = (const float*)d_in[6];
    float* out = (float*)d_out;

    __half *p_act, *p_as, *p_par, *p_hx, *p_hwi, *p_hwo, *p_hswiT, *p_hswoT;
    cudaGetSymbolAddress((void**)&p_act,   g_act);
    cudaGetSymbolAddress((void**)&p_as,    g_as);
    cudaGetSymbolAddress((void**)&p_par,   g_par);
    cudaGetSymbolAddress((void**)&p_hx,    g_hx);
    cudaGetSymbolAddress((void**)&p_hwi,   g_hwi);
    cudaGetSymbolAddress((void**)&p_hwo,   g_hwo);
    cudaGetSymbolAddress((void**)&p_hswiT, g_hswiT);
    cudaGetSymbolAddress((void**)&p_hswoT, g_hswoT);

    const int SMEM_UP = 3 * U_SSB;   // 82944
    const int SMEM_DN = 3 * D_SSB;   // 81408

    cudaFuncSetAttribute(up_gemm,   cudaFuncAttributeMaxDynamicSharedMemorySize, SMEM_UP);
    cudaFuncSetAttribute(down_gemm, cudaFuncAttributeMaxDynamicSharedMemorySize, SMEM_DN);

    // merged prep: gating + sWi/sWo transposes + f2h, one launch
    prep_kernel<<<GB + TR1B + TR2B + F2HB, 256>>>(x, gate_w, bias, Wi, Wo, sWi, sWo);

    // merged up: z<8 experts -> g_act, z=8 shared -> g_as
    up_gemm<<<dim3(I_DIM / 128, T_TOK / 128, 9), 512, SMEM_UP>>>(p_hx, p_hwi, p_hswiT);

    // merged down (NN-only): z<8 expert scatter -> g_par (fp16), z=8 shared -> out
    down_gemm<<<dim3(H_DIM / 256, T_TOK / 128, 9), 512, SMEM_DN>>>(
        p_act, p_as, p_hwo, p_hswoT, p_par, out);

    // out += par pairs; re-zeroes g_count for next replay
    final_add_kernel<<<(T_TOK * H_DIM / 4) / 256, 256>>>(out);
}

// round 16
// speedup vs baseline: 1.0418x; 1.0273x over previous
#include <cuda_runtime.h>
#include <cuda_fp16.h>
#include <math.h>
#include <stdint.h>

#define T_TOK 4096
#define H_DIM 768
#define I_DIM 1152
#define TWO_I 2304
#define E_NUM 8

// ---------------- device-global scratch ------------------------------------
__device__ int    g_count[E_NUM];               // zero-init; re-zeroed by final_add
__device__ int    g_tok[E_NUM * T_TOK];
__device__ int    g_dst[E_NUM * T_TOK];
__device__ float  g_w  [E_NUM * T_TOK];
__device__ __half g_act[(size_t)E_NUM * T_TOK * I_DIM];  // expert GLU out
__device__ __half g_as [(size_t)T_TOK * I_DIM];          // shared GLU out
__device__ __half g_par[(size_t)T_TOK * 2 * H_DIM];      // per-(t,k) down-proj (fp16)
__device__ __half g_hx   [(size_t)T_TOK * H_DIM];        // x fp16 (written by gating)
__device__ __half g_hwi  [(size_t)E_NUM * H_DIM * TWO_I];// Wi fp16 [K][2I]
__device__ __half g_hwo  [(size_t)E_NUM * I_DIM * H_DIM];// Wo fp16 [K][N] (written by up z=9)
__device__ __half g_hswiT[(size_t)H_DIM * TWO_I];        // sWi^T fp16 [K][2I]
__device__ __half g_hswoT[(size_t)I_DIM * H_DIM];        // sWo^T fp16 [K][N]

// ---------------- PTX helpers ------------------------------------------------
__device__ __forceinline__ float silu_f(float v) { return v / (1.f + __expf(-v)); }

__device__ __forceinline__ void mma16(float* c, const uint32_t* a, const uint32_t* b) {
    asm volatile(
        "mma.sync.aligned.m16n8k16.row.col.f32.f16.f16.f32 "
        "{%0,%1,%2,%3},{%4,%5,%6,%7},{%8,%9},{%0,%1,%2,%3};"
        : "+f"(c[0]), "+f"(c[1]), "+f"(c[2]), "+f"(c[3])
        : "r"(a[0]), "r"(a[1]), "r"(a[2]), "r"(a[3]), "r"(b[0]), "r"(b[1]));
}
__device__ __forceinline__ void ldsm4(uint32_t* r, uint32_t a) {
    asm volatile("ldmatrix.sync.aligned.m8n8.x4.shared.b16 {%0,%1,%2,%3}, [%4];"
                 : "=r"(r[0]), "=r"(r[1]), "=r"(r[2]), "=r"(r[3]) : "r"(a));
}
__device__ __forceinline__ void ldsm4t(uint32_t* r, uint32_t a) {
    asm volatile("ldmatrix.sync.aligned.m8n8.x4.trans.shared.b16 {%0,%1,%2,%3}, [%4];"
                 : "=r"(r[0]), "=r"(r[1]), "=r"(r[2]), "=r"(r[3]) : "r"(a));
}
__device__ __forceinline__ void cpa16(uint32_t dst, const void* src) {
    asm volatile("cp.async.cg.shared.global [%0], [%1], 16;" :: "r"(dst), "l"(src));
}
__device__ __forceinline__ void cpa_commit() {
    asm volatile("cp.async.commit_group;" ::: "memory");
}
template <int NWAIT>
__device__ __forceinline__ void cpa_wait() {
    asm volatile("cp.async.wait_group %0;" :: "n"(NWAIT) : "memory");
}

// ---------------- merged prep: gating(+x f2h) + transposes + Wi f2h ------------
#define GB   512                             // gating blocks (T_TOK/8)
#define TR1B 1728                            // sWi transpose (24 x 72)
#define TR2B 864                             // sWo transpose (36 x 24)
#define N8_WI  ((long)E_NUM * H_DIM * TWO_I / 8)
#define F2HB   ((int)((N8_WI + 255) / 256))

__global__ void __launch_bounds__(256)
prep_kernel(const float* __restrict__ x,   const float* __restrict__ gate_w,
            const float* __restrict__ bias, const float* __restrict__ wi,
            const float* __restrict__ swi,  const float* __restrict__ swo) {
    __shared__ float sbuf[E_NUM * H_DIM];    // 24 KB, reused by all branches
    int b = blockIdx.x;
    int tid = threadIdx.x;

    if (b < GB) {
        // ---------- gating + x->fp16 ----------
        for (int i = tid; i < E_NUM * H_DIM; i += 256) sbuf[i] = gate_w[i];
        __syncthreads();

        int warp = tid >> 5, lane = tid & 31;
        int t = b * 8 + warp;
        const float* xr = x + (size_t)t * H_DIM;
        __half* hxr = g_hx + (size_t)t * H_DIM;

        float acc[E_NUM];
#pragma unroll
        for (int e = 0; e < E_NUM; e++) acc[e] = 0.f;
        for (int h = lane; h < H_DIM; h += 32) {
            float xv = xr[h];
            hxr[h] = __float2half(xv);
#pragma unroll
            for (int e = 0; e < E_NUM; e++) acc[e] += xv * sbuf[e * H_DIM + h];
        }
#pragma unroll
        for (int e = 0; e < E_NUM; e++) {
            float v = acc[e];
#pragma unroll
            for (int o = 16; o > 0; o >>= 1) v += __shfl_down_sync(0xffffffffu, v, o);
            acc[e] = v;
        }
        if (lane == 0) {
            float logit[E_NUM];
#pragma unroll
            for (int e = 0; e < E_NUM; e++) logit[e] = 1.f / (1.f + expf(-acc[e]));
            int i0 = 0; float b0 = -1e30f;
#pragma unroll
            for (int e = 0; e < E_NUM; e++) {
                float s = logit[e] + bias[e];
                if (s > b0) { b0 = s; i0 = e; }
            }
            int i1 = 0; float b1 = -1e30f;
#pragma unroll
            for (int e = 0; e < E_NUM; e++) {
                if (e == i0) continue;
                float s = logit[e] + bias[e];
                if (s > b1) { b1 = s; i1 = e; }
            }
            float w0 = logit[i0], w1 = logit[i1];
            float inv = 1.f / (w0 + w1);
            w0 *= inv; w1 *= inv;
            int p0 = atomicAdd(&g_count[i0], 1);
            g_tok[i0 * T_TOK + p0] = t; g_dst[i0 * T_TOK + p0] = 2 * t;     g_w[i0 * T_TOK + p0] = w0;
            int p1 = atomicAdd(&g_count[i1], 1);
            g_tok[i1 * T_TOK + p1] = t; g_dst[i1 * T_TOK + p1] = 2 * t + 1; g_w[i1 * T_TOK + p1] = w1;
        }
    } else if (b < GB + TR1B) {
        // ---------- sWi transpose: [2I][H] f32 -> [H][2I] f16 ----------
        float (*tile)[33] = (float (*)[33])sbuf;
        int bb = b - GB;
        int c0 = (bb % 24) * 32;   // H
        int r0 = (bb / 24) * 32;   // 2I
        int tx = tid & 31, ty = tid >> 5;
#pragma unroll
        for (int i = 0; i < 32; i += 8)
            tile[ty + i][tx] = swi[(size_t)(r0 + ty + i) * H_DIM + c0 + tx];
        __syncthreads();
#pragma unroll
        for (int i = 0; i < 32; i += 8)
            g_hswiT[(size_t)(c0 + ty + i) * TWO_I + r0 + tx] = __float2half(tile[tx][ty + i]);
    } else if (b < GB + TR1B + TR2B) {
        // ---------- sWo transpose: [H][I] f32 -> [I][H] f16 ----------
        float (*tile)[33] = (float (*)[33])sbuf;
        int bb = b - GB - TR1B;
        int c0 = (bb % 36) * 32;   // I (cols of src)
        int r0 = (bb / 36) * 32;   // H (rows of src)
        int tx = tid & 31, ty = tid >> 5;
#pragma unroll
        for (int i = 0; i < 32; i += 8)
            tile[ty + i][tx] = swo[(size_t)(r0 + ty + i) * I_DIM + c0 + tx];
        __syncthreads();
#pragma unroll
        for (int i = 0; i < 32; i += 8)
            g_hswoT[(size_t)(c0 + ty + i) * H_DIM + r0 + tx] = __float2half(tile[tx][ty + i]);
    } else {
        // ---------- f2h convert (Wi only) ----------
        long i = (long)(b - GB - TR1B - TR2B) * 256 + tid;
        if (i >= N8_WI) return;
        const float4* s = (const float4*)wi + i * 2;
        float4 a = s[0], bb4 = s[1];
        __half2 h0 = __floats2half2_rn(a.x, a.y);
        __half2 h1 = __floats2half2_rn(a.z, a.w);
        __half2 h2 = __floats2half2_rn(bb4.x, bb4.y);
        __half2 h3 = __floats2half2_rn(bb4.z, bb4.w);
        uint4 v = { *(uint32_t*)&h0, *(uint32_t*)&h1, *(uint32_t*)&h2, *(uint32_t*)&h3 };
        ((uint4*)g_hwi)[i] = v;
    }
}

// ================= UP GEMM (merged, z=10): R11 core + Wo f2h tail slice ========
#define U_ASTR  80u
#define U_ATILE 10240u
#define U_BT    8704u
#define U_SSB   (U_ATILE + 2 * U_BT)
#define WO_UNITS ((long)E_NUM * I_DIM * H_DIM / 8)   // 884736 = 288*512*6

__global__ void __launch_bounds__(512, 1)
up_gemm(const __half* __restrict__ Xh, const __half* __restrict__ Wih,
        const __half* __restrict__ sWiTh, const float* __restrict__ Wof) {
    constexpr int K = H_DIM, NC = K / 32;
    int tid = threadIdx.x;

    if (blockIdx.z == 9) {
        // ---- Wo f32 -> f16 (fills up_gemm tail waves; needed only by down) ----
        long base = ((long)blockIdx.y * 9 + blockIdx.x) * 512 + tid;  // 0..147455
#pragma unroll
        for (int k = 0; k < 6; k++) {
            long off = base + (long)k * 147456;
            const float4* s = (const float4*)Wof + off * 2;
            float4 a = s[0], b = s[1];
            __half2 h0 = __floats2half2_rn(a.x, a.y);
            __half2 h1 = __floats2half2_rn(a.z, a.w);
            __half2 h2 = __floats2half2_rn(b.x, b.y);
            __half2 h3 = __floats2half2_rn(b.z, b.w);
            uint4 v = { *(uint32_t*)&h0, *(uint32_t*)&h1, *(uint32_t*)&h2, *(uint32_t*)&h3 };
            ((uint4*)g_hwo)[off] = v;
        }
        return;
    }

    int e = blockIdx.z;
    bool sh = (e == 8);
    int cnt = sh ? T_TOK : g_count[e];
    int bm  = blockIdx.y * 128;
    if (bm >= cnt) return;
    int c0  = blockIdx.x * 128;

    extern __shared__ char smc[];
    uint32_t smaddr = (uint32_t)__cvta_generic_to_shared(smc);

    int am = tid >> 2, aseg = tid & 3;
    int apos = bm + am;
    long arow;
    if (sh) arow = apos;
    else    arow = g_tok[e * T_TOK + ((apos < cnt) ? apos : (cnt - 1))];
    const __half* aSrc = Xh + (size_t)arow * K + aseg * 8;
    uint32_t aDst = (uint32_t)am * U_ASTR + aseg * 16;

    const __half* Bbase = sh ? sWiTh : (Wih + (size_t)e * K * TWO_I);
    int kr = tid >> 4, n8 = tid & 15;
    const __half* bSrc0 = Bbase + (size_t)kr * TWO_I + c0 + n8 * 8;
    const __half* bSrc1 = bSrc0 + I_DIM;
    uint32_t bDst0 = U_ATILE + (uint32_t)kr * 272 + n8 * 16;
    uint32_t bDst1 = bDst0 + U_BT;

    float acc[2][8][4];
#pragma unroll
    for (int i = 0; i < 2; i++)
#pragma unroll
        for (int j = 0; j < 8; j++)
#pragma unroll
            for (int q = 0; q < 4; q++) acc[i][j][q] = 0.f;

#pragma unroll
    for (int s = 0; s < 2; s++) {
        uint32_t base = smaddr + s * U_SSB;
        cpa16(base + aDst, aSrc + s * 32);
        cpa16(base + bDst0, bSrc0 + (size_t)s * 32 * TWO_I);
        cpa16(base + bDst1, bSrc1 + (size_t)s * 32 * TWO_I);
        cpa_commit();
    }

    int warp = tid >> 5, lane = tid & 31;
    int wm = warp >> 2, wn = warp & 3;

    uint32_t aLd = (uint32_t)(wm * 32 + (lane & 15)) * U_ASTR + (lane >> 4) * 16;
    uint32_t bLd = U_ATILE + (uint32_t)(lane & 15) * 272 + (wn * 4 + (lane >> 4)) * 16;

    for (int c = 0; c < NC; c++) {
        cpa_wait<1>();
        __syncthreads();

        int pf = c + 2;
        if (pf < NC) {
            uint32_t base = smaddr + (uint32_t)(pf % 3) * U_SSB;
            cpa16(base + aDst, aSrc + pf * 32);
            cpa16(base + bDst0, bSrc0 + (size_t)pf * 32 * TWO_I);
            cpa16(base + bDst1, bSrc1 + (size_t)pf * 32 * TWO_I);
        }
        cpa_commit();

        uint32_t sbase = smaddr + (uint32_t)(c % 3) * U_SSB;
#pragma unroll
        for (int ks = 0; ks < 2; ks++) {
            uint32_t af[2][4], bf[2][2][4];
#pragma unroll
            for (int mi = 0; mi < 2; mi++)
                ldsm4(af[mi], sbase + aLd + mi * (16 * U_ASTR) + ks * 32);
#pragma unroll
            for (int t = 0; t < 2; t++)
#pragma unroll
                for (int p = 0; p < 2; p++)
                    ldsm4t(bf[t][p], sbase + bLd + t * U_BT + p * 32 +
                           (uint32_t)ks * (16 * 272));
#pragma unroll
            for (int mi = 0; mi < 2; mi++)
#pragma unroll
                for (int t = 0; t < 2; t++)
#pragma unroll
                    for (int p = 0; p < 2; p++)
#pragma unroll
                        for (int j = 0; j < 2; j++) {
                            uint32_t b2[2] = { bf[t][p][j * 2], bf[t][p][j * 2 + 1] };
                            mma16(acc[mi][t * 4 + p * 2 + j], af[mi], b2);
                        }
        }
    }

    int g = lane >> 2, q = lane & 3;
#pragma unroll
    for (int mi = 0; mi < 2; mi++) {
        int r0 = bm + wm * 32 + mi * 16 + g;
        int r1 = r0 + 8;
        long o0 = -1, o1 = -1;
        float w0 = 1.f, w1 = 1.f;
        __half* C;
        if (sh) {
            C = g_as; o0 = r0; o1 = r1;
        } else {
            C = g_act;
            if (r0 < cnt) { o0 = (long)e * T_TOK + r0; w0 = g_w[e * T_TOK + r0]; }
            if (r1 < cnt) { o1 = (long)e * T_TOK + r1; w1 = g_w[e * T_TOK + r1]; }
        }
#pragma unroll
        for (int nidx = 0; nidx < 4; nidx++) {
            int col = c0 + wn * 32 + (nidx >> 1) * 16 + (nidx & 1) * 8 + 2 * q;
            float p0 = acc[mi][nidx][0],     p1 = acc[mi][nidx][1];
            float p2 = acc[mi][nidx][2],     p3 = acc[mi][nidx][3];
            float g0 = acc[mi][4 + nidx][0], g1 = acc[mi][4 + nidx][1];
            float g2 = acc[mi][4 + nidx][2], g3 = acc[mi][4 + nidx][3];
            if (o0 >= 0) {
                float v0 = sh ? silu_f(p0) * g0 : silu_f(g0) * p0 * w0;
                float v1 = sh ? silu_f(p1) * g1 : silu_f(g1) * p1 * w0;
                *(__half2*)&C[o0 * I_DIM + col] = __floats2half2_rn(v0, v1);
            }
            if (o1 >= 0) {
                float v0 = sh ? silu_f(p2) * g2 : silu_f(g2) * p2 * w1;
                float v1 = sh ? silu_f(p3) * g3 : silu_f(g3) * p3 * w1;
                *(__half2*)&C[o1 * I_DIM + col] = __floats2half2_rn(v0, v1);
            }
        }
    }
}

// ================= DOWN GEMM (merged, z=9): R11 core, fp16 par =================
#define D_ASTR  80u
#define D_ATILE 10240u
#define D_BSTR  528u
#define D_BT    (32u * D_BSTR)      // 16896
#define D_SSB   (D_ATILE + D_BT)    // 27136

__global__ void __launch_bounds__(512, 1)
down_gemm(const __half* __restrict__ Acth, const __half* __restrict__ Ash,
          const __half* __restrict__ Woh,  const __half* __restrict__ sWoTh,
          __half* __restrict__ Par, float* __restrict__ Out) {
    constexpr int N = H_DIM, K = I_DIM, NC = K / 32;

    int e = blockIdx.z;
    bool sh = (e == 8);
    int cnt = sh ? T_TOK : g_count[e];
    int bm  = blockIdx.y * 128;
    if (bm >= cnt) return;
    int bn  = blockIdx.x * 256;

    extern __shared__ char smc[];
    uint32_t smaddr = (uint32_t)__cvta_generic_to_shared(smc);
    int tid = threadIdx.x;

    int am = tid >> 2, aseg = tid & 3;
    int apos = bm + am;
    long arow = sh ? apos : ((long)e * T_TOK + ((apos < cnt) ? apos : 0));
    const __half* Abase = sh ? Ash : Acth;
    const __half* aSrc = Abase + (size_t)arow * K + aseg * 8;
    uint32_t aDst = (uint32_t)am * D_ASTR + aseg * 16;

    const __half* Bbase = sh ? sWoTh : (Woh + (size_t)e * K * N);
    int kr = tid >> 4, bs = tid & 15;
    const __half* bSrc = Bbase + (size_t)kr * N + bn + bs * 16;
    uint32_t bDst = D_ATILE + (uint32_t)kr * D_BSTR + bs * 32;

    float acc[2][8][4];
#pragma unroll
    for (int i = 0; i < 2; i++)
#pragma unroll
        for (int j = 0; j < 8; j++)
#pragma unroll
            for (int q = 0; q < 4; q++) acc[i][j][q] = 0.f;

#pragma unroll
    for (int s = 0; s < 2; s++) {
        uint32_t base = smaddr + s * D_SSB;
        cpa16(base + aDst, aSrc + s * 32);
        cpa16(base + bDst,      bSrc + (size_t)s * 32 * N);
        cpa16(base + bDst + 16, bSrc + (size_t)s * 32 * N + 8);
        cpa_commit();
    }

    int warp = tid >> 5, lane = tid & 31;
    int wm = warp >> 2, wn = warp & 3;

    uint32_t aLd = (uint32_t)(wm * 32 + (lane & 15)) * D_ASTR + (lane >> 4) * 16;
    uint32_t bLd = D_ATILE + (uint32_t)(lane & 15) * D_BSTR + (wn * 8 + (lane >> 4)) * 16;

    for (int c = 0; c < NC; c++) {
        cpa_wait<1>();
        __syncthreads();

        int pf = c + 2;
        if (pf < NC) {
            uint32_t base = smaddr + (uint32_t)(pf % 3) * D_SSB;
            cpa16(base + aDst, aSrc + pf * 32);
            cpa16(base + bDst,      bSrc + (size_t)pf * 32 * N);
            cpa16(base + bDst + 16, bSrc + (size_t)pf * 32 * N + 8);
        }
        cpa_commit();

        uint32_t sbase = smaddr + (uint32_t)(c % 3) * D_SSB;
#pragma unroll
        for (int ks = 0; ks < 2; ks++) {
            uint32_t af[2][4], bf[4][4];
#pragma unroll
            for (int mi = 0; mi < 2; mi++)
                ldsm4(af[mi], sbase + aLd + mi * (16 * D_ASTR) + ks * 32);
#pragma unroll
            for (int p = 0; p < 4; p++)
                ldsm4t(bf[p], sbase + bLd + p * 32 + (uint32_t)ks * (16 * D_BSTR));
#pragma unroll
            for (int mi = 0; mi < 2; mi++)
#pragma unroll
                for (int p = 0; p < 4; p++)
#pragma unroll
                    for (int j = 0; j < 2; j++) {
                        uint32_t b2[2] = { bf[p][j * 2], bf[p][j * 2 + 1] };
                        mma16(acc[mi][p * 2 + j], af[mi], b2);
                    }
        }
    }

    int g = lane >> 2, q = lane & 3;
#pragma unroll
    for (int mi = 0; mi < 2; mi++) {
        int r0 = bm + wm * 32 + mi * 16 + g;
        int r1 = r0 + 8;
        if (sh) {
#pragma unroll
            for (int ni = 0; ni < 8; ni++) {
                int cx = bn + wn * 64 + ni * 8 + 2 * q;
                float2 v0 = { acc[mi][ni][0], acc[mi][ni][1] };
                float2 v1 = { acc[mi][ni][2], acc[mi][ni][3] };
                *(float2*)&Out[(size_t)r0 * H_DIM + cx] = v0;
                *(float2*)&Out[(size_t)r1 * H_DIM + cx] = v1;
            }
        } else {
            long o0 = (r0 < cnt) ? (long)g_dst[e * T_TOK + r0] : -1;
            long o1 = (r1 < cnt) ? (long)g_dst[e * T_TOK + r1] : -1;
#pragma unroll
            for (int ni = 0; ni < 8; ni++) {
                int cx = bn + wn * 64 + ni * 8 + 2 * q;
                if (o0 >= 0)
                    *(__half2*)&Par[o0 * H_DIM + cx] =
                        __floats2half2_rn(acc[mi][ni][0], acc[mi][ni][1]);
                if (o1 >= 0)
                    *(__half2*)&Par[o1 * H_DIM + cx] =
                        __floats2half2_rn(acc[mi][ni][2], acc[mi][ni][3]);
            }
        }
    }
}

// ---------------- final add: out += par[2t] + par[2t+1] (fp16 par) -------------
__global__ void __launch_bounds__(256)
final_add_kernel(float* __restrict__ out) {
    int idx4 = blockIdx.x * 256 + threadIdx.x;   // over T*H/4
    if (blockIdx.x == 0 && threadIdx.x < E_NUM) g_count[threadIdx.x] = 0;
    int h4 = idx4 % (H_DIM / 4);
    int t  = idx4 / (H_DIM / 4);
    float4 o = ((float4*)out)[idx4];
    const uint2 a0 = *(const uint2*)(g_par + (size_t)(2 * t) * H_DIM + h4 * 4);
    const uint2 a1 = *(const uint2*)(g_par + (size_t)(2 * t + 1) * H_DIM + h4 * 4);
    __half2 p00 = *(__half2*)&a0.x, p01 = *(__half2*)&a0.y;
    __half2 p10 = *(__half2*)&a1.x, p11 = *(__half2*)&a1.y;
    float2 f00 = __half22float2(p00), f01 = __half22float2(p01);
    float2 f10 = __half22float2(p10), f11 = __half22float2(p11);
    o.x += f00.x + f10.x;
    o.y += f00.y + f10.y;
    o.z += f01.x + f11.x;
    o.w += f01.y + f11.y;
    ((float4*)out)[idx4] = o;
}

// ---------------- launch ---------------------------------------------------------
extern "C" void kernel_launch(void* const* d_in, const int* in_sizes, int n_in,
                              void* d_out, int out_size) {
    const float* x      = (const float*)d_in[0];
    const float* gate_w = (const float*)d_in[1];
    const float* bias   = (const float*)d_in[2];
    const float* Wi     = (const float*)d_in[3];
    const float* Wo     = (const float*)d_in[4];
    const float* sWi    = (const float*)d_in[5];
    const float* sWo    = (const float*)d_in[6];
    float* out = (float*)d_out;

    __half *p_act, *p_as, *p_par, *p_hx, *p_hwi, *p_hwo, *p_hswiT, *p_hswoT;
    cudaGetSymbolAddress((void**)&p_act,   g_act);
    cudaGetSymbolAddress((void**)&p_as,    g_as);
    cudaGetSymbolAddress((void**)&p_par,   g_par);
    cudaGetSymbolAddress((void**)&p_hx,    g_hx);
    cudaGetSymbolAddress((void**)&p_hwi,   g_hwi);
    cudaGetSymbolAddress((void**)&p_hwo,   g_hwo);
    cudaGetSymbolAddress((void**)&p_hswiT, g_hswiT);
    cudaGetSymbolAddress((void**)&p_hswoT, g_hswoT);

    const int SMEM_UP = 3 * U_SSB;   // 82944
    const int SMEM_DN = 3 * D_SSB;   // 81408

    cudaFuncSetAttribute(up_gemm,   cudaFuncAttributeMaxDynamicSharedMemorySize, SMEM_UP);
    cudaFuncSetAttribute(down_gemm, cudaFuncAttributeMaxDynamicSharedMemorySize, SMEM_DN);

    // merged prep: gating(+x f2h) + sWi/sWo transposes + Wi f2h
    prep_kernel<<<GB + TR1B + TR2B + F2HB, 256>>>(x, gate_w, bias, Wi, sWi, sWo);

    // merged up: z<8 experts -> g_act, z=8 shared -> g_as, z=9 Wo f2h (tail)
    up_gemm<<<dim3(I_DIM / 128, T_TOK / 128, 10), 512, SMEM_UP>>>(p_hx, p_hwi, p_hswiT, Wo);

    // merged down (NN-only): z<8 expert scatter -> g_par (fp16), z=8 shared -> out
    down_gemm<<<dim3(H_DIM / 256, T_TOK / 128, 9), 512, SMEM_DN>>>(
        p_act, p_as, p_hwo, p_hswoT, p_par, out);

    // out += par pairs; re-zeroes g_count for next replay
    final_add_kernel<<<(T_TOK * H_DIM / 4) / 256, 256>>>(out);
}